// round 16
// baseline (speedup 1.0000x reference)
#include <cuda_runtime.h>
#include <cuda_fp16.h>
#include <math.h>
#include <stdint.h>

#define N_NODES 100000
#define SEQ 16

// Scratch activations as fp16 (device globals: no allocation).
__device__ __align__(16) __half g_h0[N_NODES * 16];
__device__ __align__(16) __half g_h1[N_NODES * 32];
__device__ __align__(16) __half g_h2[N_NODES * 64];
__device__ __align__(16) __half g_h3[N_NODES * 128];
__device__ int g_idx[N_NODES * SEQ];
__device__ int g_is64;
// weights as fp16 (prepared once per launch)
__device__ __align__(16) __half g_w1[32 * 256];
__device__ __align__(16) __half g_w2[64 * 512];
__device__ __align__(16) __half g_w3[128 * 1024];
__device__ __align__(16) __half g_f1[256 * 128];

__device__ __forceinline__ float elu(float v) {
    return v > 0.f ? v : expm1f(v);
}

// ---------------- helpers ----------------
__device__ __forceinline__ uint32_t smem_to_u32(const void* p) {
    uint32_t a;
    asm("{ .reg .u64 tmp; cvta.to.shared.u64 tmp, %1; cvt.u32.u64 %0, tmp; }"
        : "=r"(a) : "l"(p));
    return a;
}
#define SWZ(b) ((b) ^ (((b) >> 3) & 0x70))

__device__ __forceinline__ void ldsm_x4(uint32_t* r, uint32_t addr) {
    asm volatile(
        "ldmatrix.sync.aligned.m8n8.x4.shared.b16 {%0,%1,%2,%3}, [%4];"
        : "=r"(r[0]), "=r"(r[1]), "=r"(r[2]), "=r"(r[3]) : "r"(addr));
}
__device__ __forceinline__ void mma_f16(float* c, const uint32_t* a,
                                        uint32_t b0, uint32_t b1) {
    asm volatile(
        "mma.sync.aligned.m16n8k16.row.col.f32.f16.f16.f32 "
        "{%0,%1,%2,%3}, {%4,%5,%6,%7}, {%8,%9}, {%0,%1,%2,%3};"
        : "+f"(c[0]), "+f"(c[1]), "+f"(c[2]), "+f"(c[3])
        : "r"(a[0]), "r"(a[1]), "r"(a[2]), "r"(a[3]), "r"(b0), "r"(b1));
}
__device__ __forceinline__ void cp16(uint32_t dst, const void* src) {
    asm volatile("cp.async.ca.shared.global [%0], [%1], 16;"
                 :: "r"(dst), "l"(src));
}
#define CP_COMMIT() asm volatile("cp.async.commit_group;" ::: "memory")
#define CP_WAIT0()  asm volatile("cp.async.wait_group 0;" ::: "memory")
#define CP_WAIT1()  asm volatile("cp.async.wait_group 1;" ::: "memory")

__device__ __forceinline__ uint32_t packh2(float a, float b) {
    __half2 h = __floats2half2_rn(a, b);
    return *reinterpret_cast<uint32_t*>(&h);
}

// ---------------------------------------------------------------------------
// Index dtype detection + conversion (reference declares int64; JAX default
// x64-off actually yields int32 — detect on device, clamp for safety).
// ---------------------------------------------------------------------------
__global__ void detect_idx_kernel(const int* __restrict__ w32) {
    if (threadIdx.x == 0) {
        int all_zero = 1;
        for (int k = 0; k < 64; k++) {
            if (w32[2 * k * 1024 + 1] != 0) { all_zero = 0; break; }
        }
        g_is64 = all_zero;
    }
}
__global__ void conv_idx_kernel(const int* __restrict__ w32) {
    int i = blockIdx.x * blockDim.x + threadIdx.x;
    if (i >= N_NODES * SEQ) return;
    int v = g_is64 ? w32[2 * i] : w32[i];
    if (v < 0) v = 0;
    if (v >= N_NODES) v = N_NODES - 1;
    g_idx[i] = v;
}

// ---------------------------------------------------------------------------
// Fused prep: blocks [0,800) convert all weights fp32->fp16;
// blocks [800, 800+391) run fc0 (keeps launch #3 = L1 mma for ncu).
// ---------------------------------------------------------------------------
__global__ __launch_bounds__(256) void prep_kernel(
    const float* __restrict__ w1, const float* __restrict__ w2,
    const float* __restrict__ w3, const float* __restrict__ f1,
    const float* __restrict__ x,
    const float* __restrict__ fc0_w, const float* __restrict__ fc0_b)
{
    if (blockIdx.x < 800) {
        int i = blockIdx.x * 256 + threadIdx.x;   // 0 .. 204799
        const float* src;
        __half* dst;
        int off;
        if (i < 8192)              { src = w1; dst = g_w1; off = i; }
        else if (i < 40960)        { src = w2; dst = g_w2; off = i - 8192; }
        else if (i < 172032)       { src = w3; dst = g_w3; off = i - 40960; }
        else                       { src = f1; dst = g_f1; off = i - 172032; }
        dst[off] = __float2half_rn(src[off]);
        return;
    }

    // fc0 part
    __shared__ float sw[48];
    __shared__ float sb[16];
    if (threadIdx.x < 48) sw[threadIdx.x] = fc0_w[threadIdx.x];
    if (threadIdx.x < 16) sb[threadIdx.x] = fc0_b[threadIdx.x];
    __syncthreads();

    int n = (blockIdx.x - 800) * 256 + threadIdx.x;
    if (n >= N_NODES) return;

    float x0 = x[n * 3 + 0], x1 = x[n * 3 + 1], x2 = x[n * 3 + 2];
    uint32_t h[8];
#pragma unroll
    for (int j = 0; j < 8; j++) {
        float v0 = sb[2 * j] + sw[(2 * j) * 3] * x0 + sw[(2 * j) * 3 + 1] * x1 +
                   sw[(2 * j) * 3 + 2] * x2;
        float v1 = sb[2 * j + 1] + sw[(2 * j + 1) * 3] * x0 +
                   sw[(2 * j + 1) * 3 + 1] * x1 + sw[(2 * j + 1) * 3 + 2] * x2;
        h[j] = packh2(elu(v0), elu(v1));
    }
    uint4* dh = reinterpret_cast<uint4*>(g_h0 + (size_t)n * 16);
    dh[0] = make_uint4(h[0], h[1], h[2], h[3]);
    dh[1] = make_uint4(h[4], h[5], h[6], h[7]);
}

// ---------------------------------------------------------------------------
// Warp-MMA gathered GEMM (layers 1-3): fp16 x fp16, fp32 accum.
// BM=128 x OT per block, 256 threads (8 warps as 4x2, warp tile 32 x WN).
// BK=64 k-slab; cp.async gather-copy, 3-stage ring, 2 blocks/SM (R13 best).
// ---------------------------------------------------------------------------
template <int K, int OTOT, int OT, int C>
__global__ __launch_bounds__(256, 2) void mma_gemm_kernel(
    const __half* __restrict__ pa,
    const __half* __restrict__ wg,
    const float* __restrict__ bias,
    __half* __restrict__ oh)
{
    constexpr int BM     = 128;
    constexpr int THREADS = 256;
    constexpr int NSLAB  = K / 64;
    constexpr int WN     = OT / 2;
    constexpr int NT     = WN / 8;
    constexpr int NT2    = WN / 16;
    constexpr int ACH    = BM * 8 / THREADS;
    constexpr int BTOT   = OT * 8;
    constexpr int BCH    = (BTOT + THREADS - 1) / THREADS;
    constexpr uint32_t ABYTES = BM * 128;
    constexpr uint32_t BBYTES = OT * 128;
    constexpr uint32_t BUF    = ABYTES + BBYTES;
    constexpr int NBUF   = 3;

    extern __shared__ char smem[];
    const uint32_t sbu = smem_to_u32(smem);
    int* sIdx = reinterpret_cast<int*>(smem + NBUF * BUF);

    const int t    = threadIdx.x;
    const int wid  = t >> 5;
    const int lane = t & 31;
    const int wm   = wid & 3;
    const int wn   = wid >> 2;
    const int gid  = lane >> 2;
    const int tid  = lane & 3;
    const int n0   = blockIdx.x * BM;

    for (int i = t; i < BM * SEQ; i += THREADS) {
        int node = n0 + (i >> 4);
        if (node > N_NODES - 1) node = N_NODES - 1;
        sIdx[i] = g_idx[node * SEQ + (i & 15)];
    }
    __syncthreads();

    auto issue_copy = [&](int s, int buf) {
        uint32_t base = sbu + buf * BUF;
#pragma unroll
        for (int j = 0; j < ACH; j++) {
            int id  = t + THREADS * j;
            int row = id >> 3;
            int c   = id & 7;
            int kg  = s * 64 + c * 8;
            int sn  = sIdx[row * SEQ + kg / C];
            const __half* src = pa + (size_t)sn * C + (kg % C);
            uint32_t dst = base + SWZ((uint32_t)(row * 128 + c * 16));
            cp16(dst, src);
        }
#pragma unroll
        for (int j = 0; j < BCH; j++) {
            int id = t + THREADS * j;
            if (id < BTOT) {
                int o = id >> 3;
                int c = id & 7;
                const __half* src = wg + (size_t)o * K + s * 64 + c * 8;
                uint32_t dst = base + ABYTES +
                               SWZ((uint32_t)(o * 128 + c * 16));
                cp16(dst, src);
            }
        }
        CP_COMMIT();
    };

    float acc[2][NT][4];
#pragma unroll
    for (int m = 0; m < 2; m++)
#pragma unroll
        for (int n = 0; n < NT; n++)
#pragma unroll
            for (int q = 0; q < 4; q++) acc[m][n][q] = 0.f;

    issue_copy(0, 0);
    if (NSLAB > 1) issue_copy(1, 1);
    if (NSLAB > 1) CP_WAIT1(); else CP_WAIT0();
    __syncthreads();

    const uint32_t flrow  = lane & 15;
    const uint32_t fchalf = (lane >> 4) * 16;

    for (int s = 0; s < NSLAB; s++) {
        const int buf = s % NBUF;
        if (s + 2 < NSLAB) issue_copy(s + 2, (s + 2) % NBUF);

        uint32_t base = sbu + buf * BUF;
#pragma unroll
        for (int kc = 0; kc < 4; kc++) {
            uint32_t colb = kc * 32 + fchalf;
            uint32_t ah[2][4];
            uint32_t fh[NT2][4];
#pragma unroll
            for (int mt = 0; mt < 2; mt++) {
                uint32_t off = (wm * 32 + mt * 16 + flrow) * 128 + colb;
                ldsm_x4(ah[mt], base + SWZ(off));
            }
#pragma unroll
            for (int n2 = 0; n2 < NT2; n2++) {
                uint32_t off = (wn * WN + n2 * 16 + flrow) * 128 + colb;
                ldsm_x4(fh[n2], base + ABYTES + SWZ(off));
            }
#pragma unroll
            for (int n2 = 0; n2 < NT2; n2++) {
#pragma unroll
                for (int mt = 0; mt < 2; mt++) {
                    mma_f16(acc[mt][n2 * 2],     ah[mt], fh[n2][0], fh[n2][2]);
                    mma_f16(acc[mt][n2 * 2 + 1], ah[mt], fh[n2][1], fh[n2][3]);
                }
            }
        }

        if (s + 1 < NSLAB) {
            if (s + 2 < NSLAB) CP_WAIT1(); else CP_WAIT0();
            __syncthreads();
        }
    }

    // ---- epilogue: bias + ELU; fp16 output ----
#pragma unroll
    for (int mt = 0; mt < 2; mt++) {
#pragma unroll
        for (int nt = 0; nt < NT; nt++) {
            int col = wn * WN + nt * 8 + tid * 2;
            float b0 = bias[col], b1 = bias[col + 1];
            int r0 = n0 + wm * 32 + mt * 16 + gid;
            int r1 = r0 + 8;
            if (r0 < N_NODES)
                *reinterpret_cast<uint32_t*>(oh + (size_t)r0 * OTOT + col) =
                    packh2(elu(acc[mt][nt][0] + b0), elu(acc[mt][nt][1] + b1));
            if (r1 < N_NODES)
                *reinterpret_cast<uint32_t*>(oh + (size_t)r1 * OTOT + col) =
                    packh2(elu(acc[mt][nt][2] + b0), elu(acc[mt][nt][3] + b1));
        }
    }
}

// ---------------------------------------------------------------------------
// Fused fc1 + fc2 + log_softmax. BM=128 nodes, OT=256 (full fc1 row),
// 512 threads = 16 warps as 4 (M) x 4 (N); K=128 dense from h3.
// fc1 epilogue -> padded smem tile [128][264] fp16; then one warp per 8
// nodes computes fc2 logits + log_softmax from smem.
// ---------------------------------------------------------------------------
#define F12_SMEM 98304
__global__ __launch_bounds__(512, 1) void fc12_kernel(
    const __half* __restrict__ pa,       // h3 [N,128]
    const __half* __restrict__ wg,       // fc1_w fp16 [256,128]
    const float* __restrict__ bias,      // fc1_b [256]
    const float* __restrict__ w2f,       // fc2_w fp32 [12,256]
    const float* __restrict__ b2f,       // fc2_b [12]
    float* __restrict__ out)
{
    constexpr int K = 128, OT = 256, BM = 128, THREADS = 512;
    constexpr int WN = 64, NT = 8, NT2 = 4;
    constexpr uint32_t ABYTES = BM * 128;      // 16 KB
    constexpr uint32_t BBYTES = OT * 128;      // 32 KB
    constexpr uint32_t BUF    = ABYTES + BBYTES;   // 48 KB, 2 buffers

    extern __shared__ char smem[];
    const uint32_t sbu = smem_to_u32(smem);

    const int t    = threadIdx.x;
    const int wid  = t >> 5;
    const int lane = t & 31;
    const int wm   = wid & 3;
    const int wn   = wid >> 2;       // 0..3
    const int gid  = lane >> 2;
    const int tid  = lane & 3;
    const int n0   = blockIdx.x * BM;

    auto issue_copy = [&](int s, int buf) {
        uint32_t base = sbu + buf * BUF;
#pragma unroll
        for (int j = 0; j < 2; j++) {          // A: 128*8/512 = 2
            int id  = t + THREADS * j;
            int row = id >> 3;
            int c   = id & 7;
            int node = n0 + row;
            if (node > N_NODES - 1) node = N_NODES - 1;
            const __half* src = pa + (size_t)node * K + s * 64 + c * 8;
            cp16(base + SWZ((uint32_t)(row * 128 + c * 16)), src);
        }
#pragma unroll
        for (int j = 0; j < 4; j++) {          // B: 256*8/512 = 4
            int id = t + THREADS * j;
            int o  = id >> 3;
            int c  = id & 7;
            const __half* src = wg + (size_t)o * K + s * 64 + c * 8;
            cp16(base + ABYTES + SWZ((uint32_t)(o * 128 + c * 16)), src);
        }
        CP_COMMIT();
    };

    float acc[2][NT][4];
#pragma unroll
    for (int m = 0; m < 2; m++)
#pragma unroll
        for (int n = 0; n < NT; n++)
#pragma unroll
            for (int q = 0; q < 4; q++) acc[m][n][q] = 0.f;

    issue_copy(0, 0);
    issue_copy(1, 1);
    CP_WAIT1();
    __syncthreads();

    const uint32_t flrow  = lane & 15;
    const uint32_t fchalf = (lane >> 4) * 16;

#pragma unroll
    for (int s = 0; s < 2; s++) {
        uint32_t base = sbu + s * BUF;
#pragma unroll
        for (int kc = 0; kc < 4; kc++) {
            uint32_t colb = kc * 32 + fchalf;
            uint32_t ah[2][4];
            uint32_t fh[NT2][4];
#pragma unroll
            for (int mt = 0; mt < 2; mt++) {
                uint32_t off = (wm * 32 + mt * 16 + flrow) * 128 + colb;
                ldsm_x4(ah[mt], base + SWZ(off));
            }
#pragma unroll
            for (int n2 = 0; n2 < NT2; n2++) {
                uint32_t off = (wn * WN + n2 * 16 + flrow) * 128 + colb;
                ldsm_x4(fh[n2], base + ABYTES + SWZ(off));
            }
#pragma unroll
            for (int n2 = 0; n2 < NT2; n2++) {
#pragma unroll
                for (int mt = 0; mt < 2; mt++) {
                    mma_f16(acc[mt][n2 * 2],     ah[mt], fh[n2][0], fh[n2][2]);
                    mma_f16(acc[mt][n2 * 2 + 1], ah[mt], fh[n2][1], fh[n2][3]);
                }
            }
        }
        if (s == 0) { CP_WAIT0(); __syncthreads(); }
    }

    __syncthreads();   // all smem reads done; safe to repurpose

    // ---- fc1 epilogue into smem tile [128][264] fp16 (conflict-free) ----
    __half* sh4 = reinterpret_cast<__half*>(smem);
    float*  sw  = reinterpret_cast<float*>(smem + 68608);   // [12][256]
    float*  sbb = reinterpret_cast<float*>(smem + 80896);   // [12]

#pragma unroll
    for (int mt = 0; mt < 2; mt++) {
#pragma unroll
        for (int nt = 0; nt < NT; nt++) {
            int col = wn * WN + nt * 8 + tid * 2;
            float b0 = bias[col], b1 = bias[col + 1];
            int rl0 = wm * 32 + mt * 16 + gid;
            int rl1 = rl0 + 8;
            *reinterpret_cast<uint32_t*>(sh4 + rl0 * 264 + col) =
                packh2(elu(acc[mt][nt][0] + b0), elu(acc[mt][nt][1] + b1));
            *reinterpret_cast<uint32_t*>(sh4 + rl1 * 264 + col) =
                packh2(elu(acc[mt][nt][2] + b0), elu(acc[mt][nt][3] + b1));
        }
    }
    for (int i = t; i < 12 * 256; i += THREADS) sw[i] = w2f[i];
    if (t < 12) sbb[t] = b2f[t];
    __syncthreads();

    // ---- fc2 + log_softmax: warp wid handles 8 nodes ----
#pragma unroll
    for (int q = 0; q < 8; q++) {
        int nl   = wid * 8 + q;
        int node = n0 + nl;
        float a12[12];
#pragma unroll
        for (int o = 0; o < 12; o++) a12[o] = 0.f;
#pragma unroll
        for (int r = 0; r < 4; r++) {
            uint32_t u = *reinterpret_cast<const uint32_t*>(
                sh4 + nl * 264 + 2 * (lane + 32 * r));
            __half2 h2 = *reinterpret_cast<const __half2*>(&u);
            float2 f = __half22float2(h2);
            int col = 2 * (lane + 32 * r);
#pragma unroll
            for (int o = 0; o < 12; o++)
                a12[o] += f.x * sw[o * 256 + col] + f.y * sw[o * 256 + col + 1];
        }
#pragma unroll
        for (int o = 0; o < 12; o++) {
#pragma unroll
            for (int d = 16; d > 0; d >>= 1)
                a12[o] += __shfl_xor_sync(0xffffffffu, a12[o], d);
            a12[o] += sbb[o];
        }
        float m = a12[0];
#pragma unroll
        for (int o = 1; o < 12; o++) m = fmaxf(m, a12[o]);
        float ssum = 0.f;
#pragma unroll
        for (int o = 0; o < 12; o++) ssum += expf(a12[o] - m);
        float lse = m + logf(ssum);
        if (lane < 12 && node < N_NODES)
            out[(size_t)node * 12 + lane] = a12[lane] - lse;
    }
}

// ---------------------------------------------------------------------------
// Launch
// ---------------------------------------------------------------------------
extern "C" void kernel_launch(void* const* d_in, const int* in_sizes, int n_in,
                              void* d_out, int out_size)
{
    const float* x      = (const float*)d_in[0];
    const int*   idxw   = (const int*)d_in[1];
    const float* fc0_w  = (const float*)d_in[2];
    const float* fc0_b  = (const float*)d_in[3];
    const float* w1     = (const float*)d_in[4];
    const float* b1     = (const float*)d_in[5];
    const float* w2     = (const float*)d_in[6];
    const float* b2     = (const float*)d_in[7];
    const float* w3     = (const float*)d_in[8];
    const float* b3     = (const float*)d_in[9];
    const float* fc1_w  = (const float*)d_in[10];
    const float* fc1_b  = (const float*)d_in[11];
    const float* fc2_w  = (const float*)d_in[12];
    const float* fc2_b  = (const float*)d_in[13];
    float* out = (float*)d_out;

    __half *h0, *h1, *h2, *h3;
    cudaGetSymbolAddress((void**)&h0, g_h0);
    cudaGetSymbolAddress((void**)&h1, g_h1);
    cudaGetSymbolAddress((void**)&h2, g_h2);
    cudaGetSymbolAddress((void**)&h3, g_h3);

    __half *gw1, *gw2, *gw3, *gf1;
    cudaGetSymbolAddress((void**)&gw1, g_w1);
    cudaGetSymbolAddress((void**)&gw2, g_w2);
    cudaGetSymbolAddress((void**)&gw3, g_w3);
    cudaGetSymbolAddress((void**)&gf1, g_f1);

    // dynamic smem: 3 * (16K A + OT*128 B) + 8K idx
    const int SM_L1  = 3 * (16384 + 32 * 128) + 8192;     //  69632
    const int SM_L2  = 3 * (16384 + 64 * 128) + 8192;     //  81920
    const int SM_L3  = 3 * (16384 + 128 * 128) + 8192;    // 106496

    static int attr_set = 0;
    if (!attr_set) {
        cudaFuncSetAttribute(mma_gemm_kernel<256, 32, 32, 16>,
                             cudaFuncAttributeMaxDynamicSharedMemorySize, SM_L1);
        cudaFuncSetAttribute(mma_gemm_kernel<512, 64, 64, 32>,
                             cudaFuncAttributeMaxDynamicSharedMemorySize, SM_L2);
        cudaFuncSetAttribute(mma_gemm_kernel<1024, 128, 128, 64>,
                             cudaFuncAttributeMaxDynamicSharedMemorySize, SM_L3);
        cudaFuncSetAttribute(fc12_kernel,
                             cudaFuncAttributeMaxDynamicSharedMemorySize, F12_SMEM);
        attr_set = 1;
    }

    const int NB = (N_NODES + 127) / 128;   // 782 blocks

    detect_idx_kernel<<<1, 32>>>(idxw);                               // 0
    conv_idx_kernel<<<(N_NODES * SEQ + 255) / 256, 256>>>(idxw);      // 1
    prep_kernel<<<800 + (N_NODES + 255) / 256, 256>>>(                // 2
        w1, w2, w3, fc1_w, x, fc0_w, fc0_b);

    // spiral conv 1: C=16, K=256, O=32                               // 3 (ncu)
    mma_gemm_kernel<256, 32, 32, 16><<<NB, 256, SM_L1>>>(
        h0, gw1, b1, h1);
    // spiral conv 2: C=32, K=512, O=64                               // 4
    mma_gemm_kernel<512, 64, 64, 32><<<NB, 256, SM_L2>>>(
        h1, gw2, b2, h2);
    // spiral conv 3: C=64, K=1024, O=128                             // 5
    mma_gemm_kernel<1024, 128, 128, 64><<<NB, 256, SM_L3>>>(
        h2, gw3, b3, h3);
    // fused fc1 + fc2 + log_softmax                                  // 6
    fc12_kernel<<<NB, 512, F12_SMEM>>>(h3, gf1, fc1_b, fc2_w, fc2_b, out);
}

// round 17
// speedup vs baseline: 1.1166x; 1.1166x over previous
#include <cuda_runtime.h>
#include <cuda_fp16.h>
#include <math.h>
#include <stdint.h>

#define N_NODES 100000
#define SEQ 16

// Scratch activations as fp16 (device globals: no allocation).
__device__ __align__(16) __half g_h0[N_NODES * 16];
__device__ __align__(16) __half g_h1[N_NODES * 32];
__device__ __align__(16) __half g_h2[N_NODES * 64];
__device__ __align__(16) __half g_h3[N_NODES * 128];
__device__ __align__(16) __half g_h4[N_NODES * 256];
__device__ int g_idx[N_NODES * SEQ];
// weights as fp16 (prepared once per launch)
__device__ __align__(16) __half g_w1[32 * 256];
__device__ __align__(16) __half g_w2[64 * 512];
__device__ __align__(16) __half g_w3[128 * 1024];
__device__ __align__(16) __half g_f1[256 * 128];

__device__ __forceinline__ float elu(float v) {
    return v > 0.f ? v : expm1f(v);
}

// ---------------- helpers ----------------
__device__ __forceinline__ uint32_t smem_to_u32(const void* p) {
    uint32_t a;
    asm("{ .reg .u64 tmp; cvta.to.shared.u64 tmp, %1; cvt.u32.u64 %0, tmp; }"
        : "=r"(a) : "l"(p));
    return a;
}
#define SWZ(b) ((b) ^ (((b) >> 3) & 0x70))

__device__ __forceinline__ void ldsm_x4(uint32_t* r, uint32_t addr) {
    asm volatile(
        "ldmatrix.sync.aligned.m8n8.x4.shared.b16 {%0,%1,%2,%3}, [%4];"
        : "=r"(r[0]), "=r"(r[1]), "=r"(r[2]), "=r"(r[3]) : "r"(addr));
}
__device__ __forceinline__ void mma_f16(float* c, const uint32_t* a,
                                        uint32_t b0, uint32_t b1) {
    asm volatile(
        "mma.sync.aligned.m16n8k16.row.col.f32.f16.f16.f32 "
        "{%0,%1,%2,%3}, {%4,%5,%6,%7}, {%8,%9}, {%0,%1,%2,%3};"
        : "+f"(c[0]), "+f"(c[1]), "+f"(c[2]), "+f"(c[3])
        : "r"(a[0]), "r"(a[1]), "r"(a[2]), "r"(a[3]), "r"(b0), "r"(b1));
}
// L2-only async copy (no L1 fill; data is consumed from smem, never from L1)
__device__ __forceinline__ void cp16(uint32_t dst, const void* src) {
    asm volatile("cp.async.cg.shared.global [%0], [%1], 16;"
                 :: "r"(dst), "l"(src));
}
#define CP_COMMIT() asm volatile("cp.async.commit_group;" ::: "memory")
#define CP_WAIT0()  asm volatile("cp.async.wait_group 0;" ::: "memory")
#define CP_WAIT1()  asm volatile("cp.async.wait_group 1;" ::: "memory")

__device__ __forceinline__ uint32_t packh2(float a, float b) {
    __half2 h = __floats2half2_rn(a, b);
    return *reinterpret_cast<uint32_t*>(&h);
}

// ---------------------------------------------------------------------------
// ONE fused prep kernel:
//   blocks [0, 6250)          : idx dtype-detect (per block, L2-hit scan) +
//                               int64/int32 conversion + clamp
//   blocks [6250, 7050)       : weight fp32 -> fp16 conversion
//   blocks [7050, 7050+391)   : fc0 + ELU -> fp16 h0
// ---------------------------------------------------------------------------
#define PREP_IDX_BLK  6250
#define PREP_W_BLK    800
#define PREP_FC0_BLK  391
__global__ __launch_bounds__(256) void prep_kernel(
    const int* __restrict__ idxw,
    const float* __restrict__ w1, const float* __restrict__ w2,
    const float* __restrict__ w3, const float* __restrict__ f1,
    const float* __restrict__ x,
    const float* __restrict__ fc0_w, const float* __restrict__ fc0_b)
{
    if (blockIdx.x < PREP_IDX_BLK) {
        // --- per-block is64 detection: if the buffer is little-endian int64
        //     with values < 2^31, every odd 32-bit word is zero.
        __shared__ int s_all0;
        if (threadIdx.x == 0) s_all0 = 1;
        __syncthreads();
        if (threadIdx.x < 64 && idxw[2 * (int)threadIdx.x * 1024 + 1] != 0)
            s_all0 = 0;
        __syncthreads();
        const int is64 = s_all0;

        int i = blockIdx.x * 256 + threadIdx.x;
        if (i < N_NODES * SEQ) {
            int v = is64 ? idxw[2 * i] : idxw[i];
            if (v < 0) v = 0;
            if (v >= N_NODES) v = N_NODES - 1;
            g_idx[i] = v;
        }
        return;
    }
    if (blockIdx.x < PREP_IDX_BLK + PREP_W_BLK) {
        int i = (blockIdx.x - PREP_IDX_BLK) * 256 + threadIdx.x;  // < 204800
        const float* src;
        __half* dst;
        int off;
        if (i < 8192)              { src = w1; dst = g_w1; off = i; }
        else if (i < 40960)        { src = w2; dst = g_w2; off = i - 8192; }
        else if (i < 172032)       { src = w3; dst = g_w3; off = i - 40960; }
        else                       { src = f1; dst = g_f1; off = i - 172032; }
        dst[off] = __float2half_rn(src[off]);
        return;
    }

    // fc0 part
    __shared__ float sw[48];
    __shared__ float sb[16];
    if (threadIdx.x < 48) sw[threadIdx.x] = fc0_w[threadIdx.x];
    if (threadIdx.x < 16) sb[threadIdx.x] = fc0_b[threadIdx.x];
    __syncthreads();

    int n = (blockIdx.x - PREP_IDX_BLK - PREP_W_BLK) * 256 + threadIdx.x;
    if (n >= N_NODES) return;

    float x0 = x[n * 3 + 0], x1 = x[n * 3 + 1], x2 = x[n * 3 + 2];
    uint32_t h[8];
#pragma unroll
    for (int j = 0; j < 8; j++) {
        float v0 = sb[2 * j] + sw[(2 * j) * 3] * x0 + sw[(2 * j) * 3 + 1] * x1 +
                   sw[(2 * j) * 3 + 2] * x2;
        float v1 = sb[2 * j + 1] + sw[(2 * j + 1) * 3] * x0 +
                   sw[(2 * j + 1) * 3 + 1] * x1 + sw[(2 * j + 1) * 3 + 2] * x2;
        h[j] = packh2(elu(v0), elu(v1));
    }
    uint4* dh = reinterpret_cast<uint4*>(g_h0 + (size_t)n * 16);
    dh[0] = make_uint4(h[0], h[1], h[2], h[3]);
    dh[1] = make_uint4(h[4], h[5], h[6], h[7]);
}

// ---------------------------------------------------------------------------
// Warp-MMA gathered GEMM: fp16 x fp16, fp32 accum, single term.
// BM=128 x OT per block, 256 threads (8 warps as 4x2, warp tile 32 x WN).
// BK=64 k-slab; cp.async.cg gather-copy into swizzled smem, 3-stage ring,
// 2 blocks/SM (R13/R15 proven best config).
// C: input channels per neighbor (0 = dense).
// ---------------------------------------------------------------------------
template <int K, int OTOT, int OT, int C, bool SPLIT>
__global__ __launch_bounds__(256, 2) void mma_gemm_kernel(
    const __half* __restrict__ pa,
    const __half* __restrict__ wg,
    const float* __restrict__ bias,
    float* __restrict__ outf,
    __half* __restrict__ oh)
{
    constexpr int BM     = 128;
    constexpr int THREADS = 256;
    constexpr int NSLAB  = K / 64;
    constexpr int WN     = OT / 2;
    constexpr int NT     = WN / 8;
    constexpr int NT2    = WN / 16;
    constexpr int ACH    = BM * 8 / THREADS;
    constexpr int BTOT   = OT * 8;
    constexpr int BCH    = (BTOT + THREADS - 1) / THREADS;
    constexpr uint32_t ABYTES = BM * 128;
    constexpr uint32_t BBYTES = OT * 128;
    constexpr uint32_t BUF    = ABYTES + BBYTES;
    constexpr int NBUF   = 3;

    extern __shared__ char smem[];
    const uint32_t sbu = smem_to_u32(smem);
    int* sIdx = reinterpret_cast<int*>(smem + NBUF * BUF);

    const int t    = threadIdx.x;
    const int wid  = t >> 5;
    const int lane = t & 31;
    const int wm   = wid & 3;
    const int wn   = wid >> 2;
    const int gid  = lane >> 2;
    const int tid  = lane & 3;
    const int n0   = blockIdx.x * BM;
    const int o_off = blockIdx.y * OT;

    if constexpr (C > 0) {
        for (int i = t; i < BM * SEQ; i += THREADS) {
            int node = n0 + (i >> 4);
            if (node > N_NODES - 1) node = N_NODES - 1;
            sIdx[i] = g_idx[node * SEQ + (i & 15)];
        }
        __syncthreads();
    }

    auto issue_copy = [&](int s, int buf) {
        uint32_t base = sbu + buf * BUF;
#pragma unroll
        for (int j = 0; j < ACH; j++) {
            int id  = t + THREADS * j;
            int row = id >> 3;
            int c   = id & 7;
            int kg  = s * 64 + c * 8;
            const __half* src;
            if constexpr (C == 0) {
                int node = n0 + row;
                if (node > N_NODES - 1) node = N_NODES - 1;
                src = pa + (size_t)node * K + kg;
            } else {
                int sn = sIdx[row * SEQ + kg / C];
                src = pa + (size_t)sn * C + (kg % C);
            }
            uint32_t dst = base + SWZ((uint32_t)(row * 128 + c * 16));
            cp16(dst, src);
        }
#pragma unroll
        for (int j = 0; j < BCH; j++) {
            int id = t + THREADS * j;
            if (id < BTOT) {
                int o = id >> 3;
                int c = id & 7;
                const __half* src =
                    wg + (size_t)(o_off + o) * K + s * 64 + c * 8;
                uint32_t dst = base + ABYTES +
                               SWZ((uint32_t)(o * 128 + c * 16));
                cp16(dst, src);
            }
        }
        CP_COMMIT();
    };

    float acc[2][NT][4];
#pragma unroll
    for (int m = 0; m < 2; m++)
#pragma unroll
        for (int n = 0; n < NT; n++)
#pragma unroll
            for (int q = 0; q < 4; q++) acc[m][n][q] = 0.f;

    // prologue: fill up to 2 slabs ahead
    issue_copy(0, 0);
    if (NSLAB > 1) issue_copy(1, 1);
    if (NSLAB > 1) CP_WAIT1(); else CP_WAIT0();
    __syncthreads();

    const uint32_t flrow  = lane & 15;
    const uint32_t fchalf = (lane >> 4) * 16;

    for (int s = 0; s < NSLAB; s++) {
        const int buf = s % NBUF;
        if (s + 2 < NSLAB) issue_copy(s + 2, (s + 2) % NBUF);

        uint32_t base = sbu + buf * BUF;
#pragma unroll
        for (int kc = 0; kc < 4; kc++) {
            uint32_t colb = kc * 32 + fchalf;
            uint32_t ah[2][4];
            uint32_t fh[NT2][4];
#pragma unroll
            for (int mt = 0; mt < 2; mt++) {
                uint32_t off = (wm * 32 + mt * 16 + flrow) * 128 + colb;
                ldsm_x4(ah[mt], base + SWZ(off));
            }
#pragma unroll
            for (int n2 = 0; n2 < NT2; n2++) {
                uint32_t off = (wn * WN + n2 * 16 + flrow) * 128 + colb;
                ldsm_x4(fh[n2], base + ABYTES + SWZ(off));
            }
#pragma unroll
            for (int n2 = 0; n2 < NT2; n2++) {
#pragma unroll
                for (int mt = 0; mt < 2; mt++) {
                    mma_f16(acc[mt][n2 * 2],     ah[mt], fh[n2][0], fh[n2][2]);
                    mma_f16(acc[mt][n2 * 2 + 1], ah[mt], fh[n2][1], fh[n2][3]);
                }
            }
        }

        if (s + 1 < NSLAB) {
            if (s + 2 < NSLAB) CP_WAIT1(); else CP_WAIT0();
            __syncthreads();
        }
    }

    // ---- epilogue: bias + ELU; fp32 or fp16 output ----
#pragma unroll
    for (int mt = 0; mt < 2; mt++) {
#pragma unroll
        for (int nt = 0; nt < NT; nt++) {
            int col = o_off + wn * WN + nt * 8 + tid * 2;
            float b0 = bias[col], b1 = bias[col + 1];
            int r0 = n0 + wm * 32 + mt * 16 + gid;
            int r1 = r0 + 8;
            float v0 = elu(acc[mt][nt][0] + b0);
            float v1 = elu(acc[mt][nt][1] + b1);
            float v2 = elu(acc[mt][nt][2] + b0);
            float v3 = elu(acc[mt][nt][3] + b1);
            if constexpr (SPLIT) {
                if (r0 < N_NODES)
                    *reinterpret_cast<uint32_t*>(oh + (size_t)r0 * OTOT + col) =
                        packh2(v0, v1);
                if (r1 < N_NODES)
                    *reinterpret_cast<uint32_t*>(oh + (size_t)r1 * OTOT + col) =
                        packh2(v2, v3);
            } else {
                if (r0 < N_NODES) {
                    float2 v; v.x = v0; v.y = v1;
                    *reinterpret_cast<float2*>(outf + (size_t)r0 * OTOT + col) = v;
                }
                if (r1 < N_NODES) {
                    float2 v; v.x = v2; v.y = v3;
                    *reinterpret_cast<float2*>(outf + (size_t)r1 * OTOT + col) = v;
                }
            }
        }
    }
}

// ---------------------------------------------------------------------------
// fc2 + log_softmax: one warp per node. 12 outputs from 256 fp16 inputs.
// ---------------------------------------------------------------------------
__global__ __launch_bounds__(256) void fc2_lsm_kernel(
    const float* __restrict__ w,
    const float* __restrict__ bias,
    float* __restrict__ out)
{
    __shared__ float sw[12][256];
    __shared__ float sb[12];
    int t = threadIdx.x;
    for (int i = t; i < 12 * 256; i += 256) sw[i >> 8][i & 255] = w[i];
    if (t < 12) sb[t] = bias[t];
    __syncthreads();

    int node = blockIdx.x * 8 + (t >> 5);
    int lane = t & 31;
    if (node >= N_NODES) return;

    const __half2* row2 =
        reinterpret_cast<const __half2*>(g_h4 + (size_t)node * 256);
    float acc[12];
#pragma unroll
    for (int o = 0; o < 12; o++) acc[o] = 0.f;

#pragma unroll
    for (int r = 0; r < 4; r++) {
        float2 f = __half22float2(row2[lane + 32 * r]);
        int col = 2 * (lane + 32 * r);
#pragma unroll
        for (int o = 0; o < 12; o++)
            acc[o] += f.x * sw[o][col] + f.y * sw[o][col + 1];
    }

#pragma unroll
    for (int o = 0; o < 12; o++) {
#pragma unroll
        for (int d = 16; d > 0; d >>= 1)
            acc[o] += __shfl_xor_sync(0xffffffffu, acc[o], d);
        acc[o] += sb[o];
    }

    float m = acc[0];
#pragma unroll
    for (int o = 1; o < 12; o++) m = fmaxf(m, acc[o]);
    float s = 0.f;
#pragma unroll
    for (int o = 0; o < 12; o++) s += expf(acc[o] - m);
    float lse = m + logf(s);

    if (lane < 12) out[(size_t)node * 12 + lane] = acc[lane] - lse;
}

// ---------------------------------------------------------------------------
// Launch
// ---------------------------------------------------------------------------
extern "C" void kernel_launch(void* const* d_in, const int* in_sizes, int n_in,
                              void* d_out, int out_size)
{
    const float* x      = (const float*)d_in[0];
    const int*   idxw   = (const int*)d_in[1];
    const float* fc0_w  = (const float*)d_in[2];
    const float* fc0_b  = (const float*)d_in[3];
    const float* w1     = (const float*)d_in[4];
    const float* b1     = (const float*)d_in[5];
    const float* w2     = (const float*)d_in[6];
    const float* b2     = (const float*)d_in[7];
    const float* w3     = (const float*)d_in[8];
    const float* b3     = (const float*)d_in[9];
    const float* fc1_w  = (const float*)d_in[10];
    const float* fc1_b  = (const float*)d_in[11];
    const float* fc2_w  = (const float*)d_in[12];
    const float* fc2_b  = (const float*)d_in[13];
    float* out = (float*)d_out;

    __half *h0, *h1, *h2, *h3, *h4;
    cudaGetSymbolAddress((void**)&h0, g_h0);
    cudaGetSymbolAddress((void**)&h1, g_h1);
    cudaGetSymbolAddress((void**)&h2, g_h2);
    cudaGetSymbolAddress((void**)&h3, g_h3);
    cudaGetSymbolAddress((void**)&h4, g_h4);

    __half *gw1, *gw2, *gw3, *gf1;
    cudaGetSymbolAddress((void**)&gw1, g_w1);
    cudaGetSymbolAddress((void**)&gw2, g_w2);
    cudaGetSymbolAddress((void**)&gw3, g_w3);
    cudaGetSymbolAddress((void**)&gf1, g_f1);

    // dynamic smem: 3 * (16K A + OT*128 B) + 8K idx
    const int SM_L1  = 3 * (16384 + 32 * 128) + 8192;     //  69632
    const int SM_L2  = 3 * (16384 + 64 * 128) + 8192;     //  81920
    const int SM_L3  = 3 * (16384 + 128 * 128) + 8192;    // 106496
    const int SM_FC1 = SM_L3;

    static int attr_set = 0;
    if (!attr_set) {
        cudaFuncSetAttribute(mma_gemm_kernel<256, 32, 32, 16, true>,
                             cudaFuncAttributeMaxDynamicSharedMemorySize, SM_L1);
        cudaFuncSetAttribute(mma_gemm_kernel<512, 64, 64, 32, true>,
                             cudaFuncAttributeMaxDynamicSharedMemorySize, SM_L2);
        cudaFuncSetAttribute(mma_gemm_kernel<1024, 128, 128, 64, true>,
                             cudaFuncAttributeMaxDynamicSharedMemorySize, SM_L3);
        cudaFuncSetAttribute(mma_gemm_kernel<128, 256, 128, 0, true>,
                             cudaFuncAttributeMaxDynamicSharedMemorySize, SM_FC1);
        attr_set = 1;
    }

    const int NB = (N_NODES + 127) / 128;   // 782 blocks

    // ONE fused prep launch (idx detect+convert, weight fp16, fc0)
    prep_kernel<<<PREP_IDX_BLK + PREP_W_BLK + PREP_FC0_BLK, 256>>>(   // 0
        idxw, w1, w2, w3, fc1_w, x, fc0_w, fc0_b);

    // spiral conv 1: C=16, K=256, O=32                               // 1
    mma_gemm_kernel<256, 32, 32, 16, true><<<dim3(NB, 1), 256, SM_L1>>>(
        h0, gw1, b1, nullptr, h1);
    // spiral conv 2: C=32, K=512, O=64                               // 2
    mma_gemm_kernel<512, 64, 64, 32, true><<<dim3(NB, 1), 256, SM_L2>>>(
        h1, gw2, b2, nullptr, h2);
    // spiral conv 3: C=64, K=1024, O=128                             // 3
    mma_gemm_kernel<1024, 128, 128, 64, true><<<dim3(NB, 1), 256, SM_L3>>>(
        h2, gw3, b3, nullptr, h3);
    // fc1 dense: K=128, O=256 (2 output tiles), fp16 output          // 4
    mma_gemm_kernel<128, 256, 128, 0, true><<<dim3(NB, 2), 256, SM_FC1>>>(
        h3, gf1, fc1_b, nullptr, h4);
    // fc2 + log_softmax                                              // 5
    fc2_lsm_kernel<<<(N_NODES + 7) / 8, 256>>>(fc2_w, fc2_b, out);
}